// round 9
// baseline (speedup 1.0000x reference)
#include <cuda_runtime.h>
#include <cstdint>
#include <math.h>

// Problem shape (fixed by the reference)
#define NB 32
#define NT 2048
#define ND 128
#define CH 4           // timesteps per thread-chunk
#define NL 4           // lanes (d) per thread -> float4/int4 accesses
#define NC 512         // NT / CH

// ---------------------------------------------------------------------------
// Single fused kernel. Thread = (b, chunk c, lane quad q -> d4 = 4*q).
// 16 elements/thread as before, but 128-bit loads/stores halve the
// instruction count on the streaming path.
// ---------------------------------------------------------------------------
__global__ void __launch_bounds__(128) k_all(const float* __restrict__ v,
                                             const float* __restrict__ t,
                                             const void*  __restrict__ mraw,
                                             float* __restrict__ out) {
    const int gid = blockIdx.x * 128 + threadIdx.x;
    const int q  = gid & 31;                 // ND/4 = 32 lane quads
    const int c  = (gid >> 5) & (NC - 1);
    const int b  = gid >> 14;                // 5 + log2(NC)
    const int d4 = q * 4;

    const float4* v4 = (const float4*)v;
    const float4* t4 = (const float4*)t;
    float4* o4 = (float4*)out;

    const int rb  = b * NT * ND + d4;            // scalar row base (lane 0)
    const int rb4 = b * NT * (ND / 4) + q;       // float4/int4 row base
    const int base4 = rb4 + (c * CH) * (ND / 4);
    const unsigned char* m8 = (const unsigned char*)mraw;
    const int4* m32 = (const int4*)mraw;

    // ---- 1. bulk payload: 8 independent LDG.128 ----
    float4 VV[CH], TT[CH];
#pragma unroll
    for (int tt = 0; tt < CH; ++tt) {
        VV[tt] = v4[base4 + tt * (ND / 4)];
        TT[tt] = t4[base4 + tt * (ND / 4)];
    }

    // ---- 2. mask dtype detection (ballot over first 32 words) ----
    // int32 0/1 words are always <=1; packed bool bytes give a word >1 over
    // 32 words w.p. 1-(1/8)^32. Bool-as-int32 0/1 takes the int path: correct.
    __shared__ int s_isb;
    if (threadIdx.x < 32) {
        unsigned int w = ((const unsigned int*)mraw)[threadIdx.x];
        unsigned int any = __ballot_sync(0xffffffffu, w > 1u);
        if (threadIdx.x == 0) s_isb = (any != 0u);
    }
    __syncthreads();
    const bool isb = (s_isb != 0);

    // ---- chunk mask bits: 4 wide loads ----
    unsigned int bA = 0, bB = 0, bC = 0, bD = 0;
    if (isb) {
#pragma unroll
        for (int tt = 0; tt < CH; ++tt) {
            unsigned int w = *(const unsigned int*)(m8 + rb + (c * CH + tt) * ND);
            bA |= ((w         & 0xffu) ? 1u : 0u) << tt;
            bB |= (((w >> 8)  & 0xffu) ? 1u : 0u) << tt;
            bC |= (((w >> 16) & 0xffu) ? 1u : 0u) << tt;
            bD |= (((w >> 24)        ) ? 1u : 0u) << tt;
        }
    } else {
#pragma unroll
        for (int tt = 0; tt < CH; ++tt) {
            int4 w = m32[base4 + tt * (ND / 4)];
            bA |= (w.x ? 1u : 0u) << tt;
            bB |= (w.y ? 1u : 0u) << tt;
            bC |= (w.z ? 1u : 0u) << tt;
            bD |= (w.w ? 1u : 0u) << tt;
        }
    }

    // ---- 3a. forward seed probe: last observation before this chunk ----
    // Region [0, c*CH) length is a multiple of 4 -> 4-step batches stay in.
    int f0 = -1, f1 = -1, f2 = -1, f3 = -1;
    {
        int ti = c * CH - 1;
        while ((f0 < 0 || f1 < 0 || f2 < 0 || f3 < 0) && ti >= 0) {
            unsigned int x0,x1,x2,x3, y0,y1,y2,y3, z0,z1,z2,z3, u0,u1,u2,u3;
            if (isb) {
                unsigned int w0 = *(const unsigned int*)(m8 + rb + (ti    ) * ND);
                unsigned int w1 = *(const unsigned int*)(m8 + rb + (ti - 1) * ND);
                unsigned int w2 = *(const unsigned int*)(m8 + rb + (ti - 2) * ND);
                unsigned int w3 = *(const unsigned int*)(m8 + rb + (ti - 3) * ND);
                x0=w0&0xffu; x1=w1&0xffu; x2=w2&0xffu; x3=w3&0xffu;
                y0=(w0>>8)&0xffu; y1=(w1>>8)&0xffu; y2=(w2>>8)&0xffu; y3=(w3>>8)&0xffu;
                z0=(w0>>16)&0xffu; z1=(w1>>16)&0xffu; z2=(w2>>16)&0xffu; z3=(w3>>16)&0xffu;
                u0=w0>>24; u1=w1>>24; u2=w2>>24; u3=w3>>24;
            } else {
                int4 w0 = m32[rb4 + (ti    ) * (ND / 4)];
                int4 w1 = m32[rb4 + (ti - 1) * (ND / 4)];
                int4 w2 = m32[rb4 + (ti - 2) * (ND / 4)];
                int4 w3 = m32[rb4 + (ti - 3) * (ND / 4)];
                x0=w0.x; x1=w1.x; x2=w2.x; x3=w3.x;
                y0=w0.y; y1=w1.y; y2=w2.y; y3=w3.y;
                z0=w0.z; z1=w1.z; z2=w2.z; z3=w3.z;
                u0=w0.w; u1=w1.w; u2=w2.w; u3=w3.w;
            }
            if (f0 < 0) f0 = x0 ? ti : x1 ? ti-1 : x2 ? ti-2 : x3 ? ti-3 : -1;
            if (f1 < 0) f1 = y0 ? ti : y1 ? ti-1 : y2 ? ti-2 : y3 ? ti-3 : -1;
            if (f2 < 0) f2 = z0 ? ti : z1 ? ti-1 : z2 ? ti-2 : z3 ? ti-3 : -1;
            if (f3 < 0) f3 = u0 ? ti : u1 ? ti-1 : u2 ? ti-2 : u3 ? ti-3 : -1;
            ti -= 4;
        }
    }

    // ---- 3b. backward seed probe: first observation after this chunk ----
    int n0 = -1, n1 = -1, n2 = -1, n3 = -1;
    {
        int ti = (c + 1) * CH;
        while ((n0 < 0 || n1 < 0 || n2 < 0 || n3 < 0) && ti < NT) {
            unsigned int x0,x1,x2,x3, y0,y1,y2,y3, z0,z1,z2,z3, u0,u1,u2,u3;
            if (isb) {
                unsigned int w0 = *(const unsigned int*)(m8 + rb + (ti    ) * ND);
                unsigned int w1 = *(const unsigned int*)(m8 + rb + (ti + 1) * ND);
                unsigned int w2 = *(const unsigned int*)(m8 + rb + (ti + 2) * ND);
                unsigned int w3 = *(const unsigned int*)(m8 + rb + (ti + 3) * ND);
                x0=w0&0xffu; x1=w1&0xffu; x2=w2&0xffu; x3=w3&0xffu;
                y0=(w0>>8)&0xffu; y1=(w1>>8)&0xffu; y2=(w2>>8)&0xffu; y3=(w3>>8)&0xffu;
                z0=(w0>>16)&0xffu; z1=(w1>>16)&0xffu; z2=(w2>>16)&0xffu; z3=(w3>>16)&0xffu;
                u0=w0>>24; u1=w1>>24; u2=w2>>24; u3=w3>>24;
            } else {
                int4 w0 = m32[rb4 + (ti    ) * (ND / 4)];
                int4 w1 = m32[rb4 + (ti + 1) * (ND / 4)];
                int4 w2 = m32[rb4 + (ti + 2) * (ND / 4)];
                int4 w3 = m32[rb4 + (ti + 3) * (ND / 4)];
                x0=w0.x; x1=w1.x; x2=w2.x; x3=w3.x;
                y0=w0.y; y1=w1.y; y2=w2.y; y3=w3.y;
                z0=w0.z; z1=w1.z; z2=w2.z; z3=w3.z;
                u0=w0.w; u1=w1.w; u2=w2.w; u3=w3.w;
            }
            if (n0 < 0) n0 = x0 ? ti : x1 ? ti+1 : x2 ? ti+2 : x3 ? ti+3 : -1;
            if (n1 < 0) n1 = y0 ? ti : y1 ? ti+1 : y2 ? ti+2 : y3 ? ti+3 : -1;
            if (n2 < 0) n2 = z0 ? ti : z1 ? ti+1 : z2 ? ti+2 : z3 ? ti+3 : -1;
            if (n3 < 0) n3 = u0 ? ti : u1 ? ti+1 : u2 ? ti+2 : u3 ? ti+3 : -1;
            ti += 4;
        }
    }

    // ---- 4. seed gathers + fallbacks ----
    float lx0=0.f, lx1=0.f, lx2=0.f, lx3=0.f, lt0, lt1, lt2, lt3;
    if (f0 >= 0) { lx0 = v[rb + 0 + f0 * ND]; lt0 = t[rb + 0 + f0 * ND]; } else lt0 = t[rb + 0];
    if (f1 >= 0) { lx1 = v[rb + 1 + f1 * ND]; lt1 = t[rb + 1 + f1 * ND]; } else lt1 = t[rb + 1];
    if (f2 >= 0) { lx2 = v[rb + 2 + f2 * ND]; lt2 = t[rb + 2 + f2 * ND]; } else lt2 = t[rb + 2];
    if (f3 >= 0) { lx3 = v[rb + 3 + f3 * ND]; lt3 = t[rb + 3 + f3 * ND]; } else lt3 = t[rb + 3];

    float nx0=0.f, nx1=0.f, nx2=0.f, nx3=0.f, nt0, nt1, nt2, nt3;
    const int rtail = rb + (NT - 1) * ND;
    if (n0 >= 0) { nx0 = v[rb + 0 + n0 * ND]; nt0 = t[rb + 0 + n0 * ND]; } else nt0 = t[rtail + 0];
    if (n1 >= 0) { nx1 = v[rb + 1 + n1 * ND]; nt1 = t[rb + 1 + n1 * ND]; } else nt1 = t[rtail + 1];
    if (n2 >= 0) { nx2 = v[rb + 2 + n2 * ND]; nt2 = t[rb + 2 + n2 * ND]; } else nt2 = t[rtail + 2];
    if (n3 >= 0) { nx3 = v[rb + 3 + n3 * ND]; nt3 = t[rb + 3 + n3 * ND]; } else nt3 = t[rtail + 3];

    // ---- forward sweep: inclusive forward fill (consumes VV/TT) ----
    float4 LX[CH], LT[CH];
#pragma unroll
    for (int tt = 0; tt < CH; ++tt) {
        if ((bA >> tt) & 1u) { lx0 = VV[tt].x; lt0 = TT[tt].x; }
        if ((bB >> tt) & 1u) { lx1 = VV[tt].y; lt1 = TT[tt].y; }
        if ((bC >> tt) & 1u) { lx2 = VV[tt].z; lt2 = TT[tt].z; }
        if ((bD >> tt) & 1u) { lx3 = VV[tt].w; lt3 = TT[tt].w; }
        LX[tt] = make_float4(lx0, lx1, lx2, lx3);
        LT[tt] = make_float4(lt0, lt1, lt2, lt3);
    }

    // ---- backward sweep: inclusive backward fill + interpolation ----
#pragma unroll
    for (int tt = CH - 1; tt >= 0; --tt) {
        float4 o;
        {
            float xl = LX[tt].x, tl = LT[tt].x, tv = TT[tt].x;
            float den = nt0 - tl;
            float r = xl + (nx0 - xl) * __fdividef(tv - tl, den);
            bool ok = (den != 0.f) && isfinite(r);
            if ((bA >> tt) & 1u) { o.x = xl; nx0 = xl; nt0 = tv; }
            else                 { o.x = ok ? r : 0.f; }
        }
        {
            float xl = LX[tt].y, tl = LT[tt].y, tv = TT[tt].y;
            float den = nt1 - tl;
            float r = xl + (nx1 - xl) * __fdividef(tv - tl, den);
            bool ok = (den != 0.f) && isfinite(r);
            if ((bB >> tt) & 1u) { o.y = xl; nx1 = xl; nt1 = tv; }
            else                 { o.y = ok ? r : 0.f; }
        }
        {
            float xl = LX[tt].z, tl = LT[tt].z, tv = TT[tt].z;
            float den = nt2 - tl;
            float r = xl + (nx2 - xl) * __fdividef(tv - tl, den);
            bool ok = (den != 0.f) && isfinite(r);
            if ((bC >> tt) & 1u) { o.z = xl; nx2 = xl; nt2 = tv; }
            else                 { o.z = ok ? r : 0.f; }
        }
        {
            float xl = LX[tt].w, tl = LT[tt].w, tv = TT[tt].w;
            float den = nt3 - tl;
            float r = xl + (nx3 - xl) * __fdividef(tv - tl, den);
            bool ok = (den != 0.f) && isfinite(r);
            if ((bD >> tt) & 1u) { o.w = xl; nx3 = xl; nt3 = tv; }
            else                 { o.w = ok ? r : 0.f; }
        }
        o4[base4 + tt * (ND / 4)] = o;
    }
}

// ---------------------------------------------------------------------------
extern "C" void kernel_launch(void* const* d_in, const int* in_sizes, int n_in,
                              void* d_out, int out_size) {
    const float* values = (const float*)d_in[0];
    const float* times  = (const float*)d_in[1];
    const void*  mask   = d_in[2];

    (void)n_in; (void)in_sizes; (void)out_size;

    // Single fused launch: streams mask, v, t once; writes out once.
    k_all<<<(NB * NC * (ND / 4)) / 128, 128>>>(values, times, mask, (float*)d_out);
}

// round 10
// speedup vs baseline: 1.0147x; 1.0147x over previous
#include <cuda_runtime.h>
#include <cstdint>
#include <math.h>

// Problem shape (fixed by the reference)
#define NB 32
#define NT 2048
#define ND 128
#define CH 8           // timesteps per thread-chunk
#define G  4           // chunk slots per block
#define NC 256         // NT / CH
#define PAIRS 64       // ND / 2 lane pairs
#define THREADS 256    // PAIRS * G

// ---------------------------------------------------------------------------
// Single fused kernel. Block = (b, chunk group cg): 4 consecutive chunks x
// 64 lane pairs. Each thread publishes its chunk's first/last observation to
// smem; interior threads resolve seeds from smem (no global probes). Only
// slot-0 warps probe backward in time and slot-3 warps probe forward, with
// the t0/tmax fallbacks baked into the published seed values.
// ---------------------------------------------------------------------------
__global__ void __launch_bounds__(THREADS, 4)
k_all(const float* __restrict__ v, const float* __restrict__ t,
      const void* __restrict__ mraw, float* __restrict__ out) {
    __shared__ float2 s_last_x[G][PAIRS], s_last_t[G][PAIRS];   // last obs per chunk
    __shared__ float2 s_first_x[G][PAIRS], s_first_t[G][PAIRS]; // first obs per chunk
    __shared__ unsigned int s_bits[G][PAIRS];                   // bA | bB<<8
    __shared__ float2 s_extf_x[PAIRS], s_extf_t[PAIRS];         // external fwd seed
    __shared__ float2 s_extb_x[PAIRS], s_extb_t[PAIRS];         // external bwd seed
    __shared__ int s_isb;

    const int blk = blockIdx.x;
    const int b   = blk >> 6;            // blk / (NC/G)
    const int cg  = blk & 63;
    const int tid = threadIdx.x;
    const int dg  = tid & (PAIRS - 1);
    const int i   = tid >> 6;            // chunk slot 0..3 (warp-uniform)
    const int c   = cg * G + i;
    const int d2  = dg * 2;

    const float2* v2 = (const float2*)v;
    const float2* t2 = (const float2*)t;
    float2* o2 = (float2*)out;
    const unsigned char* m8 = (const unsigned char*)mraw;
    const int2* m32 = (const int2*)mraw;

    const int rb  = b * NT * ND + d2;        // scalar row base (lane 0)
    const int rb2 = b * NT * PAIRS + dg;     // float2/int2 row base
    const int base2 = rb2 + c * CH * PAIRS;

    // ---- 1. payload: 16 independent LDG.64 ----
    float2 VV[CH], TT[CH];
#pragma unroll
    for (int tt = 0; tt < CH; ++tt) {
        VV[tt] = v2[base2 + tt * PAIRS];
        TT[tt] = t2[base2 + tt * PAIRS];
    }

    // ---- 2. mask dtype detection (ballot over first 32 words) ----
    // int32 0/1 words are always <=1; packed bool bytes give a word >1 over
    // 32 words w.p. 1-(1/8)^32. Bool-as-int32 0/1 takes the int path: correct.
    if (tid < 32) {
        unsigned int w = ((const unsigned int*)mraw)[tid];
        unsigned int any = __ballot_sync(0xffffffffu, w > 1u);
        if (tid == 0) s_isb = (any != 0u);
    }
    __syncthreads();
    const bool isb = (s_isb != 0);

    // ---- 3. chunk mask bits ----
    unsigned int bA = 0, bB = 0;
    if (isb) {
#pragma unroll
        for (int tt = 0; tt < CH; ++tt) {
            unsigned short w = *(const unsigned short*)(m8 + rb + (c * CH + tt) * ND);
            bA |= ((w & 0xffu) ? 1u : 0u) << tt;
            bB |= ((w >> 8)    ? 1u : 0u) << tt;
        }
    } else {
#pragma unroll
        for (int tt = 0; tt < CH; ++tt) {
            int2 w = m32[base2 + tt * PAIRS];
            bA |= (w.x ? 1u : 0u) << tt;
            bB |= (w.y ? 1u : 0u) << tt;
        }
    }

    // ---- 4. own-chunk summaries -> smem ----
    {
        float lax0 = 0.f, lat0 = 0.f, lax1 = 0.f, lat1 = 0.f;
        float fax0 = 0.f, fat0 = 0.f, fax1 = 0.f, fat1 = 0.f;
#pragma unroll
        for (int tt = 0; tt < CH; ++tt) {              // last observed
            if ((bA >> tt) & 1u) { lax0 = VV[tt].x; lat0 = TT[tt].x; }
            if ((bB >> tt) & 1u) { lax1 = VV[tt].y; lat1 = TT[tt].y; }
        }
#pragma unroll
        for (int tt = CH - 1; tt >= 0; --tt) {         // first observed
            if ((bA >> tt) & 1u) { fax0 = VV[tt].x; fat0 = TT[tt].x; }
            if ((bB >> tt) & 1u) { fax1 = VV[tt].y; fat1 = TT[tt].y; }
        }
        s_last_x[i][dg]  = make_float2(lax0, lax1);
        s_last_t[i][dg]  = make_float2(lat0, lat1);
        s_first_x[i][dg] = make_float2(fax0, fax1);
        s_first_t[i][dg] = make_float2(fat0, fat1);
        s_bits[i][dg] = bA | (bB << 8);
    }

    // ---- 5. external probes: slot 0 -> forward seed, slot 3 -> backward ----
    if (i == 0) {
        int f0 = -1, f1 = -1;
        int ti = cg * (G * CH) - 1;          // region length multiple of 32
        if (isb) {
            while ((f0 < 0 || f1 < 0) && ti >= 0) {
                unsigned short w0 = *(const unsigned short*)(m8 + rb + (ti    ) * ND);
                unsigned short w1 = *(const unsigned short*)(m8 + rb + (ti - 1) * ND);
                unsigned short w2 = *(const unsigned short*)(m8 + rb + (ti - 2) * ND);
                unsigned short w3 = *(const unsigned short*)(m8 + rb + (ti - 3) * ND);
                if (f0 < 0) f0 = (w0 & 0xffu) ? ti : (w1 & 0xffu) ? ti-1 : (w2 & 0xffu) ? ti-2 : (w3 & 0xffu) ? ti-3 : -1;
                if (f1 < 0) f1 = (w0 >> 8) ? ti : (w1 >> 8) ? ti-1 : (w2 >> 8) ? ti-2 : (w3 >> 8) ? ti-3 : -1;
                ti -= 4;
            }
        } else {
            while ((f0 < 0 || f1 < 0) && ti >= 0) {
                int2 w0 = m32[rb2 + (ti    ) * PAIRS];
                int2 w1 = m32[rb2 + (ti - 1) * PAIRS];
                int2 w2 = m32[rb2 + (ti - 2) * PAIRS];
                int2 w3 = m32[rb2 + (ti - 3) * PAIRS];
                if (f0 < 0) f0 = w0.x ? ti : w1.x ? ti-1 : w2.x ? ti-2 : w3.x ? ti-3 : -1;
                if (f1 < 0) f1 = w0.y ? ti : w1.y ? ti-1 : w2.y ? ti-2 : w3.y ? ti-3 : -1;
                ti -= 4;
            }
        }
        float x0 = 0.f, x1 = 0.f, tv0, tv1;
        if (f0 >= 0) { x0 = v[rb + f0 * ND];     tv0 = t[rb + f0 * ND];     } else tv0 = t[rb];
        if (f1 >= 0) { x1 = v[rb + 1 + f1 * ND]; tv1 = t[rb + 1 + f1 * ND]; } else tv1 = t[rb + 1];
        s_extf_x[dg] = make_float2(x0, x1);
        s_extf_t[dg] = make_float2(tv0, tv1);
    }
    if (i == G - 1) {
        int n0 = -1, n1 = -1;
        int ti = (cg + 1) * (G * CH);
        if (isb) {
            while ((n0 < 0 || n1 < 0) && ti < NT) {
                unsigned short w0 = *(const unsigned short*)(m8 + rb + (ti    ) * ND);
                unsigned short w1 = *(const unsigned short*)(m8 + rb + (ti + 1) * ND);
                unsigned short w2 = *(const unsigned short*)(m8 + rb + (ti + 2) * ND);
                unsigned short w3 = *(const unsigned short*)(m8 + rb + (ti + 3) * ND);
                if (n0 < 0) n0 = (w0 & 0xffu) ? ti : (w1 & 0xffu) ? ti+1 : (w2 & 0xffu) ? ti+2 : (w3 & 0xffu) ? ti+3 : -1;
                if (n1 < 0) n1 = (w0 >> 8) ? ti : (w1 >> 8) ? ti+1 : (w2 >> 8) ? ti+2 : (w3 >> 8) ? ti+3 : -1;
                ti += 4;
            }
        } else {
            while ((n0 < 0 || n1 < 0) && ti < NT) {
                int2 w0 = m32[rb2 + (ti    ) * PAIRS];
                int2 w1 = m32[rb2 + (ti + 1) * PAIRS];
                int2 w2 = m32[rb2 + (ti + 2) * PAIRS];
                int2 w3 = m32[rb2 + (ti + 3) * PAIRS];
                if (n0 < 0) n0 = w0.x ? ti : w1.x ? ti+1 : w2.x ? ti+2 : w3.x ? ti+3 : -1;
                if (n1 < 0) n1 = w0.y ? ti : w1.y ? ti+1 : w2.y ? ti+2 : w3.y ? ti+3 : -1;
                ti += 4;
            }
        }
        float x0 = 0.f, x1 = 0.f, tv0, tv1;
        const int rtail = rb + (NT - 1) * ND;
        if (n0 >= 0) { x0 = v[rb + n0 * ND];     tv0 = t[rb + n0 * ND];     } else tv0 = t[rtail];
        if (n1 >= 0) { x1 = v[rb + 1 + n1 * ND]; tv1 = t[rb + 1 + n1 * ND]; } else tv1 = t[rtail + 1];
        s_extb_x[dg] = make_float2(x0, x1);
        s_extb_t[dg] = make_float2(tv0, tv1);
    }
    __syncthreads();

    // ---- 6. resolve seeds from smem (i is warp-uniform -> no divergence) ----
    float lx0, lt0, lx1, lt1;
    { float2 a = s_extf_x[dg], tb = s_extf_t[dg]; lx0 = a.x; lt0 = tb.x; lx1 = a.y; lt1 = tb.y; }
    for (int j = 0; j < i; ++j) {                 // ascending: ends at latest obs
        unsigned int wb = s_bits[j][dg];
        float2 a = s_last_x[j][dg], tb = s_last_t[j][dg];
        if (wb & 0xffu)   { lx0 = a.x; lt0 = tb.x; }
        if (wb & 0xff00u) { lx1 = a.y; lt1 = tb.y; }
    }
    float nx0, nt0, nx1, nt1;
    { float2 a = s_extb_x[dg], tb = s_extb_t[dg]; nx0 = a.x; nt0 = tb.x; nx1 = a.y; nt1 = tb.y; }
    for (int j = G - 1; j > i; --j) {             // descending: ends at nearest obs
        unsigned int wb = s_bits[j][dg];
        float2 a = s_first_x[j][dg], tb = s_first_t[j][dg];
        if (wb & 0xffu)   { nx0 = a.x; nt0 = tb.x; }
        if (wb & 0xff00u) { nx1 = a.y; nt1 = tb.y; }
    }

    // ---- 7. forward sweep: inclusive forward fill into registers ----
    float2 LX[CH], LT[CH];
#pragma unroll
    for (int tt = 0; tt < CH; ++tt) {
        if ((bA >> tt) & 1u) { lx0 = VV[tt].x; lt0 = TT[tt].x; }
        if ((bB >> tt) & 1u) { lx1 = VV[tt].y; lt1 = TT[tt].y; }
        LX[tt] = make_float2(lx0, lx1);
        LT[tt] = make_float2(lt0, lt1);
    }

    // ---- 8. backward sweep: inclusive backward fill + interpolation ----
#pragma unroll
    for (int tt = CH - 1; tt >= 0; --tt) {
        float2 o;
        {
            float xl = LX[tt].x, tl = LT[tt].x, tv = TT[tt].x;
            float den = nt0 - tl;
            float r = xl + (nx0 - xl) * __fdividef(tv - tl, den);
            bool ok = (den != 0.f) && isfinite(r);
            if ((bA >> tt) & 1u) { o.x = xl; nx0 = xl; nt0 = tv; }
            else                 { o.x = ok ? r : 0.f; }
        }
        {
            float xl = LX[tt].y, tl = LT[tt].y, tv = TT[tt].y;
            float den = nt1 - tl;
            float r = xl + (nx1 - xl) * __fdividef(tv - tl, den);
            bool ok = (den != 0.f) && isfinite(r);
            if ((bB >> tt) & 1u) { o.y = xl; nx1 = xl; nt1 = tv; }
            else                 { o.y = ok ? r : 0.f; }
        }
        o2[base2 + tt * PAIRS] = o;
    }
}

// ---------------------------------------------------------------------------
extern "C" void kernel_launch(void* const* d_in, const int* in_sizes, int n_in,
                              void* d_out, int out_size) {
    const float* values = (const float*)d_in[0];
    const float* times  = (const float*)d_in[1];
    const void*  mask   = d_in[2];

    (void)n_in; (void)in_sizes; (void)out_size;

    // Single fused launch: block = (b, chunk group); streams mask, v, t once.
    k_all<<<NB * (NC / G), THREADS>>>(values, times, mask, (float*)d_out);
}

// round 11
// speedup vs baseline: 1.0781x; 1.0625x over previous
#include <cuda_runtime.h>
#include <cstdint>
#include <math.h>

// Problem shape (fixed by the reference)
#define NB 32
#define NT 2048
#define ND 128
#define CH 8           // timesteps per thread-chunk
#define NC 256         // NT / CH

// ---------------------------------------------------------------------------
// Single fused kernel (R7 structure). Thread = (b, chunk c, lane pair).
// Ordering is deliberate: small mask loads + probes first, payload loads
// inline in the sweeps (avoids front-batched LDG bursts -> L1tex-queue
// contention / CTA spread at high occupancy).
// Register diet: only LX/LT arrays are kept; the backward sweep re-loads t
// (guaranteed L1 hits), freeing 16 regs -> 9 CTAs/SM.
// ---------------------------------------------------------------------------
__global__ void __launch_bounds__(128, 9)
k_all(const float* __restrict__ v, const float* __restrict__ t,
      const void* __restrict__ mraw, float* __restrict__ out) {
    // ---- mask dtype detection: int32 0/1 words are always <=1; packed bool
    // bytes give a word >1 over 32 words w.p. 1-(1/8)^32. Bool-as-int32 0/1
    // takes the int path, which is also correct.
    __shared__ int s_isb;
    if (threadIdx.x < 32) {
        unsigned int w = ((const unsigned int*)mraw)[threadIdx.x];
        unsigned int any = __ballot_sync(0xffffffffu, w > 1u);
        if (threadIdx.x == 0) s_isb = (any != 0u);
    }
    __syncthreads();
    const bool isb = (s_isb != 0);

    const int gid = blockIdx.x * 128 + threadIdx.x;
    const int dg = gid & 63;                 // ND/2 = 64 lane pairs
    const int c  = (gid >> 6) & (NC - 1);
    const int b  = gid >> 14;                // 6 + log2(NC)
    const int d2 = dg * 2;

    const float2* v2 = (const float2*)v;
    const float2* t2 = (const float2*)t;
    float2* o2 = (float2*)out;

    const int rb  = b * NT * ND + d2;            // scalar row base (lane 0)
    const int rb2 = b * NT * (ND / 2) + dg;      // float2/int2 row base
    const int base2 = rb2 + (c * CH) * (ND / 2);
    const unsigned char* m8 = (const unsigned char*)mraw;
    const int2* m32 = (const int2*)mraw;

    // ---- chunk mask bits (tiny loads; warp-coalesced) ----
    unsigned int bA = 0, bB = 0;
    if (isb) {
#pragma unroll
        for (int tt = 0; tt < CH; ++tt) {
            unsigned short w = *(const unsigned short*)(m8 + rb + (c * CH + tt) * ND);
            bA |= ((w & 0xffu) ? 1u : 0u) << tt;
            bB |= ((w >> 8)    ? 1u : 0u) << tt;
        }
    } else {
#pragma unroll
        for (int tt = 0; tt < CH; ++tt) {
            int2 w = m32[base2 + tt * (ND / 2)];
            bA |= (w.x ? 1u : 0u) << tt;
            bB |= (w.y ? 1u : 0u) << tt;
        }
    }

    // ---- forward seed probe: last observation before this chunk ----
    // Region [0, c*CH) has length multiple of 8 -> 4-step batches stay in.
    int f0 = -1, f1 = -1;
    {
        int ti = c * CH - 1;
        if (isb) {
            while ((f0 < 0 || f1 < 0) && ti >= 0) {
                unsigned short w0 = *(const unsigned short*)(m8 + rb + (ti    ) * ND);
                unsigned short w1 = *(const unsigned short*)(m8 + rb + (ti - 1) * ND);
                unsigned short w2 = *(const unsigned short*)(m8 + rb + (ti - 2) * ND);
                unsigned short w3 = *(const unsigned short*)(m8 + rb + (ti - 3) * ND);
                if (f0 < 0) f0 = (w0 & 0xffu) ? ti : (w1 & 0xffu) ? ti-1 : (w2 & 0xffu) ? ti-2 : (w3 & 0xffu) ? ti-3 : -1;
                if (f1 < 0) f1 = (w0 >> 8) ? ti : (w1 >> 8) ? ti-1 : (w2 >> 8) ? ti-2 : (w3 >> 8) ? ti-3 : -1;
                ti -= 4;
            }
        } else {
            while ((f0 < 0 || f1 < 0) && ti >= 0) {
                int2 w0 = m32[rb2 + (ti    ) * (ND / 2)];
                int2 w1 = m32[rb2 + (ti - 1) * (ND / 2)];
                int2 w2 = m32[rb2 + (ti - 2) * (ND / 2)];
                int2 w3 = m32[rb2 + (ti - 3) * (ND / 2)];
                if (f0 < 0) f0 = w0.x ? ti : w1.x ? ti-1 : w2.x ? ti-2 : w3.x ? ti-3 : -1;
                if (f1 < 0) f1 = w0.y ? ti : w1.y ? ti-1 : w2.y ? ti-2 : w3.y ? ti-3 : -1;
                ti -= 4;
            }
        }
    }
    float lx0 = 0.f, lx1 = 0.f, lt0, lt1;
    if (f0 >= 0) { lx0 = v[rb + f0 * ND];     lt0 = t[rb + f0 * ND];     } else lt0 = t[rb];
    if (f1 >= 0) { lx1 = v[rb + 1 + f1 * ND]; lt1 = t[rb + 1 + f1 * ND]; } else lt1 = t[rb + 1];

    // ---- forward sweep: inclusive forward fill into registers ----
    // (v and t loaded inline; only LX/LT kept live across sweeps)
    float2 LX[CH], LT[CH];
#pragma unroll
    for (int tt = 0; tt < CH; ++tt) {
        float2 vv = v2[base2 + tt * (ND / 2)];
        float2 tv = t2[base2 + tt * (ND / 2)];
        if ((bA >> tt) & 1u) { lx0 = vv.x; lt0 = tv.x; }
        if ((bB >> tt) & 1u) { lx1 = vv.y; lt1 = tv.y; }
        LX[tt] = make_float2(lx0, lx1);
        LT[tt] = make_float2(lt0, lt1);
    }

    // ---- backward seed probe: first observation after this chunk ----
    int n0i = -1, n1i = -1;
    {
        int ti = (c + 1) * CH;
        if (isb) {
            while ((n0i < 0 || n1i < 0) && ti < NT) {
                unsigned short w0 = *(const unsigned short*)(m8 + rb + (ti    ) * ND);
                unsigned short w1 = *(const unsigned short*)(m8 + rb + (ti + 1) * ND);
                unsigned short w2 = *(const unsigned short*)(m8 + rb + (ti + 2) * ND);
                unsigned short w3 = *(const unsigned short*)(m8 + rb + (ti + 3) * ND);
                if (n0i < 0) n0i = (w0 & 0xffu) ? ti : (w1 & 0xffu) ? ti+1 : (w2 & 0xffu) ? ti+2 : (w3 & 0xffu) ? ti+3 : -1;
                if (n1i < 0) n1i = (w0 >> 8) ? ti : (w1 >> 8) ? ti+1 : (w2 >> 8) ? ti+2 : (w3 >> 8) ? ti+3 : -1;
                ti += 4;
            }
        } else {
            while ((n0i < 0 || n1i < 0) && ti < NT) {
                int2 w0 = m32[rb2 + (ti    ) * (ND / 2)];
                int2 w1 = m32[rb2 + (ti + 1) * (ND / 2)];
                int2 w2 = m32[rb2 + (ti + 2) * (ND / 2)];
                int2 w3 = m32[rb2 + (ti + 3) * (ND / 2)];
                if (n0i < 0) n0i = w0.x ? ti : w1.x ? ti+1 : w2.x ? ti+2 : w3.x ? ti+3 : -1;
                if (n1i < 0) n1i = w0.y ? ti : w1.y ? ti+1 : w2.y ? ti+2 : w3.y ? ti+3 : -1;
                ti += 4;
            }
        }
    }
    float nx0 = 0.f, nx1 = 0.f, nt0, nt1;
    if (n0i >= 0) { nx0 = v[rb + n0i * ND];     nt0 = t[rb + n0i * ND];     } else nt0 = t[rb + (NT - 1) * ND];
    if (n1i >= 0) { nx1 = v[rb + 1 + n1i * ND]; nt1 = t[rb + 1 + n1i * ND]; } else nt1 = t[rb + 1 + (NT - 1) * ND];

    // ---- backward sweep: re-load t (L1 hits), backward fill + interpolate ----
#pragma unroll
    for (int tt = CH - 1; tt >= 0; --tt) {
        float2 tv2 = t2[base2 + tt * (ND / 2)];   // L1 hit: touched in fwd sweep
        float2 o;
        // lane 0
        {
            float xl = LX[tt].x, tl = LT[tt].x, tv = tv2.x;
            float den = nt0 - tl;
            float r = xl + (nx0 - xl) * __fdividef(tv - tl, den);
            bool ok = (den != 0.f) && isfinite(r);
            if ((bA >> tt) & 1u) {
                o.x = xl;                        // observed: forward fill == v
                nx0 = xl; nt0 = tv;
            } else {
                o.x = ok ? r : 0.f;
            }
        }
        // lane 1
        {
            float xl = LX[tt].y, tl = LT[tt].y, tv = tv2.y;
            float den = nt1 - tl;
            float r = xl + (nx1 - xl) * __fdividef(tv - tl, den);
            bool ok = (den != 0.f) && isfinite(r);
            if ((bB >> tt) & 1u) {
                o.y = xl;
                nx1 = xl; nt1 = tv;
            } else {
                o.y = ok ? r : 0.f;
            }
        }
        o2[base2 + tt * (ND / 2)] = o;
    }
}

// ---------------------------------------------------------------------------
extern "C" void kernel_launch(void* const* d_in, const int* in_sizes, int n_in,
                              void* d_out, int out_size) {
    const float* values = (const float*)d_in[0];
    const float* times  = (const float*)d_in[1];
    const void*  mask   = d_in[2];

    (void)n_in; (void)in_sizes; (void)out_size;

    // Single fused launch: streams mask (+small probe overage), v, t once;
    // writes out once.
    k_all<<<(NB * NC * (ND / 2)) / 128, 128>>>(values, times, mask, (float*)d_out);
}

// round 12
// speedup vs baseline: 1.2013x; 1.1143x over previous
#include <cuda_runtime.h>
#include <cstdint>
#include <math.h>

// Problem shape (fixed by the reference)
#define NB 32
#define NT 2048
#define ND 128
#define CH 8           // timesteps per thread-chunk
#define NC 256         // NT / CH
#define PD 16          // probe depth per direction (single round trip)

// ---------------------------------------------------------------------------
// Single fused kernel. Thread = (b, chunk c, lane pair).
// Probe strategy: one unconditional predicated 16-deep batch per direction
// (one memory round trip, P(fallback) ~ 2^-16 per lane), issued together with
// the chunk mask bits so all small loads share one latency window. Payload
// v/t loads stay inline in the sweeps. Backward sweep re-loads t (L1 hits).
// ---------------------------------------------------------------------------
__global__ void __launch_bounds__(128, 9)
k_all(const float* __restrict__ v, const float* __restrict__ t,
      const void* __restrict__ mraw, float* __restrict__ out) {
    // ---- mask dtype detection: int32 0/1 words are always <=1; packed bool
    // bytes give a word >1 over 32 words w.p. 1-(1/8)^32. Bool-as-int32 0/1
    // takes the int path, which is also correct.
    __shared__ int s_isb;
    if (threadIdx.x < 32) {
        unsigned int w = ((const unsigned int*)mraw)[threadIdx.x];
        unsigned int any = __ballot_sync(0xffffffffu, w > 1u);
        if (threadIdx.x == 0) s_isb = (any != 0u);
    }
    __syncthreads();
    const bool isb = (s_isb != 0);

    const int gid = blockIdx.x * 128 + threadIdx.x;
    const int dg = gid & 63;                 // ND/2 = 64 lane pairs
    const int c  = (gid >> 6) & (NC - 1);
    const int b  = gid >> 14;                // 6 + log2(NC)
    const int d2 = dg * 2;

    const float2* v2 = (const float2*)v;
    const float2* t2 = (const float2*)t;
    float2* o2 = (float2*)out;

    const int rb  = b * NT * ND + d2;            // scalar row base (lane 0)
    const int rb2 = b * NT * (ND / 2) + dg;      // float2/int2 row base
    const int base2 = rb2 + (c * CH) * (ND / 2);
    const unsigned char* m8 = (const unsigned char*)mraw;
    const int2* m32 = (const int2*)mraw;

    // ---- one latency window: chunk bits + both 16-deep probe batches ----
    unsigned int bA = 0, bB = 0;     // chunk mask bits
    unsigned int fA = 0, fB = 0;     // forward probe bits (bit k = row fstart-k)
    unsigned int nA = 0, nB = 0;     // backward probe bits (bit k = row bstart+k)
    const int fstart = c * CH - 1;
    const int bstart = (c + 1) * CH;

    if (isb) {
#pragma unroll
        for (int tt = 0; tt < CH; ++tt) {
            unsigned short w = *(const unsigned short*)(m8 + rb + (c * CH + tt) * ND);
            bA |= ((w & 0xffu) ? 1u : 0u) << tt;
            bB |= ((w >> 8)    ? 1u : 0u) << tt;
        }
#pragma unroll
        for (int k = 0; k < PD; ++k) {
            int row = fstart - k;
            unsigned short w = (row >= 0) ? *(const unsigned short*)(m8 + rb + row * ND) : (unsigned short)0;
            fA |= ((w & 0xffu) ? 1u : 0u) << k;
            fB |= ((w >> 8)    ? 1u : 0u) << k;
        }
#pragma unroll
        for (int k = 0; k < PD; ++k) {
            int row = bstart + k;
            unsigned short w = (row < NT) ? *(const unsigned short*)(m8 + rb + row * ND) : (unsigned short)0;
            nA |= ((w & 0xffu) ? 1u : 0u) << k;
            nB |= ((w >> 8)    ? 1u : 0u) << k;
        }
    } else {
#pragma unroll
        for (int tt = 0; tt < CH; ++tt) {
            int2 w = m32[base2 + tt * (ND / 2)];
            bA |= (w.x ? 1u : 0u) << tt;
            bB |= (w.y ? 1u : 0u) << tt;
        }
#pragma unroll
        for (int k = 0; k < PD; ++k) {
            int row = fstart - k;
            int2 w = (row >= 0) ? m32[rb2 + row * (ND / 2)] : make_int2(0, 0);
            fA |= (w.x ? 1u : 0u) << k;
            fB |= (w.y ? 1u : 0u) << k;
        }
#pragma unroll
        for (int k = 0; k < PD; ++k) {
            int row = bstart + k;
            int2 w = (row < NT) ? m32[rb2 + row * (ND / 2)] : make_int2(0, 0);
            nA |= (w.x ? 1u : 0u) << k;
            nB |= (w.y ? 1u : 0u) << k;
        }
    }

    // ---- resolve probe bits -> row indices (rare deep-miss fallback) ----
    int f0 = fA ? fstart - (__ffs(fA) - 1) : -1;
    int f1 = fB ? fstart - (__ffs(fB) - 1) : -1;
    int n0i = nA ? bstart + (__ffs(nA) - 1) : -1;
    int n1i = nB ? bstart + (__ffs(nB) - 1) : -1;

    {   // forward fallback: P ~ 2^-16 per lane
        int ti = fstart - PD;
        while ((f0 < 0 || f1 < 0) && ti >= 0) {
            unsigned int a, bb;
            if (isb) {
                unsigned short w = *(const unsigned short*)(m8 + rb + ti * ND);
                a = w & 0xffu; bb = w >> 8;
            } else {
                int2 w = m32[rb2 + ti * (ND / 2)];
                a = w.x; bb = w.y;
            }
            if (f0 < 0 && a)  f0 = ti;
            if (f1 < 0 && bb) f1 = ti;
            --ti;
        }
    }
    {   // backward fallback
        int ti = bstart + PD;
        while ((n0i < 0 || n1i < 0) && ti < NT) {
            unsigned int a, bb;
            if (isb) {
                unsigned short w = *(const unsigned short*)(m8 + rb + ti * ND);
                a = w & 0xffu; bb = w >> 8;
            } else {
                int2 w = m32[rb2 + ti * (ND / 2)];
                a = w.x; bb = w.y;
            }
            if (n0i < 0 && a)  n0i = ti;
            if (n1i < 0 && bb) n1i = ti;
            ++ti;
        }
    }

    // ---- seed gathers (both directions issued together) ----
    float lx0 = 0.f, lx1 = 0.f, lt0, lt1;
    if (f0 >= 0) { lx0 = v[rb + f0 * ND];     lt0 = t[rb + f0 * ND];     } else lt0 = t[rb];
    if (f1 >= 0) { lx1 = v[rb + 1 + f1 * ND]; lt1 = t[rb + 1 + f1 * ND]; } else lt1 = t[rb + 1];
    float nx0 = 0.f, nx1 = 0.f, nt0, nt1;
    if (n0i >= 0) { nx0 = v[rb + n0i * ND];     nt0 = t[rb + n0i * ND];     } else nt0 = t[rb + (NT - 1) * ND];
    if (n1i >= 0) { nx1 = v[rb + 1 + n1i * ND]; nt1 = t[rb + 1 + n1i * ND]; } else nt1 = t[rb + 1 + (NT - 1) * ND];

    // ---- forward sweep: inclusive forward fill into registers ----
    float2 LX[CH], LT[CH];
#pragma unroll
    for (int tt = 0; tt < CH; ++tt) {
        float2 vv = v2[base2 + tt * (ND / 2)];
        float2 tv = t2[base2 + tt * (ND / 2)];
        if ((bA >> tt) & 1u) { lx0 = vv.x; lt0 = tv.x; }
        if ((bB >> tt) & 1u) { lx1 = vv.y; lt1 = tv.y; }
        LX[tt] = make_float2(lx0, lx1);
        LT[tt] = make_float2(lt0, lt1);
    }

    // ---- backward sweep: re-load t (L1 hits), backward fill + interpolate ----
#pragma unroll
    for (int tt = CH - 1; tt >= 0; --tt) {
        float2 tv2 = t2[base2 + tt * (ND / 2)];   // L1 hit: touched in fwd sweep
        float2 o;
        // lane 0
        {
            float xl = LX[tt].x, tl = LT[tt].x, tv = tv2.x;
            float den = nt0 - tl;
            float r = xl + (nx0 - xl) * __fdividef(tv - tl, den);
            bool ok = (den != 0.f) && isfinite(r);
            if ((bA >> tt) & 1u) {
                o.x = xl;                        // observed: forward fill == v
                nx0 = xl; nt0 = tv;
            } else {
                o.x = ok ? r : 0.f;
            }
        }
        // lane 1
        {
            float xl = LX[tt].y, tl = LT[tt].y, tv = tv2.y;
            float den = nt1 - tl;
            float r = xl + (nx1 - xl) * __fdividef(tv - tl, den);
            bool ok = (den != 0.f) && isfinite(r);
            if ((bB >> tt) & 1u) {
                o.y = xl;
                nx1 = xl; nt1 = tv;
            } else {
                o.y = ok ? r : 0.f;
            }
        }
        o2[base2 + tt * (ND / 2)] = o;
    }
}

// ---------------------------------------------------------------------------
extern "C" void kernel_launch(void* const* d_in, const int* in_sizes, int n_in,
                              void* d_out, int out_size) {
    const float* values = (const float*)d_in[0];
    const float* times  = (const float*)d_in[1];
    const void*  mask   = d_in[2];

    (void)n_in; (void)in_sizes; (void)out_size;

    // Single fused launch: streams mask (+probe overage), v, t once;
    // writes out once.
    k_all<<<(NB * NC * (ND / 2)) / 128, 128>>>(values, times, mask, (float*)d_out);
}

// round 13
// speedup vs baseline: 1.2119x; 1.0088x over previous
#include <cuda_runtime.h>
#include <cstdint>
#include <math.h>

// Problem shape (fixed by the reference)
#define NB 32
#define NT 2048
#define ND 128
#define CH 8           // timesteps per thread-chunk
#define NC 256         // NT / CH
#define PD 12          // probe depth per direction (single round trip)

// ---------------------------------------------------------------------------
// Single fused kernel. Thread = (b, chunk c, lane pair).
// Probe strategy: one unconditional 12-deep batch per direction with
// clamped addresses + post-mask (no per-row predication), resolved via
// __ffs. P(lane needs fallback) = 2^-12. Payload v/t loads stay inline in
// the sweeps; backward sweep re-loads t (L1 hits).
// ---------------------------------------------------------------------------
__global__ void __launch_bounds__(128, 9)
k_all(const float* __restrict__ v, const float* __restrict__ t,
      const void* __restrict__ mraw, float* __restrict__ out) {
    // ---- mask dtype detection: int32 0/1 words are always <=1; packed bool
    // bytes give a word >1 over 32 words w.p. 1-(1/8)^32. Bool-as-int32 0/1
    // takes the int path, which is also correct.
    __shared__ int s_isb;
    if (threadIdx.x < 32) {
        unsigned int w = ((const unsigned int*)mraw)[threadIdx.x];
        unsigned int any = __ballot_sync(0xffffffffu, w > 1u);
        if (threadIdx.x == 0) s_isb = (any != 0u);
    }
    __syncthreads();
    const bool isb = (s_isb != 0);

    const int gid = blockIdx.x * 128 + threadIdx.x;
    const int dg = gid & 63;                 // ND/2 = 64 lane pairs
    const int c  = (gid >> 6) & (NC - 1);
    const int b  = gid >> 14;                // 6 + log2(NC)
    const int d2 = dg * 2;

    const float2* v2 = (const float2*)v;
    const float2* t2 = (const float2*)t;
    float2* o2 = (float2*)out;

    const int rb  = b * NT * ND + d2;            // scalar row base (lane 0)
    const int rb2 = b * NT * (ND / 2) + dg;      // float2/int2 row base
    const int base2 = rb2 + (c * CH) * (ND / 2);
    const unsigned char* m8 = (const unsigned char*)mraw;
    const int2* m32 = (const int2*)mraw;

    // Probe ranges + masks (range lengths are multiples of CH=8)
    const int fstart = c * CH - 1;
    const int bstart = (c + 1) * CH;
    const int vf = min(fstart + 1, PD);           // valid forward rows
    const int vb = min(NT - bstart, PD);          // valid backward rows
    const unsigned int fmask = (1u << vf) - 1u;
    const unsigned int bmask = (1u << vb) - 1u;

    // ---- one latency window: chunk bits + both probe batches ----
    unsigned int bA = 0, bB = 0;     // chunk mask bits
    unsigned int fA = 0, fB = 0;     // forward probe bits (bit k = row fstart-k)
    unsigned int nA = 0, nB = 0;     // backward probe bits (bit k = row bstart+k)

    if (isb) {
#pragma unroll
        for (int tt = 0; tt < CH; ++tt) {
            unsigned int w = *(const unsigned short*)(m8 + rb + (c * CH + tt) * ND);
            unsigned int r = __vcmpne4(w, 0u);    // 0xff per nonzero byte
            bA |= (r & 1u) << tt;
            bB |= ((r >> 8) & 1u) << tt;
        }
#pragma unroll
        for (int k = 0; k < PD; ++k) {
            int row = max(fstart - k, 0);         // clamped: always in-bounds
            unsigned int w = *(const unsigned short*)(m8 + rb + row * ND);
            unsigned int r = __vcmpne4(w, 0u);
            fA |= (r & 1u) << k;
            fB |= ((r >> 8) & 1u) << k;
        }
#pragma unroll
        for (int k = 0; k < PD; ++k) {
            int row = min(bstart + k, NT - 1);
            unsigned int w = *(const unsigned short*)(m8 + rb + row * ND);
            unsigned int r = __vcmpne4(w, 0u);
            nA |= (r & 1u) << k;
            nB |= ((r >> 8) & 1u) << k;
        }
    } else {
#pragma unroll
        for (int tt = 0; tt < CH; ++tt) {
            int2 w = m32[base2 + tt * (ND / 2)];
            bA |= (w.x ? 1u : 0u) << tt;
            bB |= (w.y ? 1u : 0u) << tt;
        }
#pragma unroll
        for (int k = 0; k < PD; ++k) {
            int row = max(fstart - k, 0);
            int2 w = m32[rb2 + row * (ND / 2)];
            fA |= (w.x ? 1u : 0u) << k;
            fB |= (w.y ? 1u : 0u) << k;
        }
#pragma unroll
        for (int k = 0; k < PD; ++k) {
            int row = min(bstart + k, NT - 1);
            int2 w = m32[rb2 + row * (ND / 2)];
            nA |= (w.x ? 1u : 0u) << k;
            nB |= (w.y ? 1u : 0u) << k;
        }
    }
    fA &= fmask; fB &= fmask;
    nA &= bmask; nB &= bmask;

    // ---- resolve probe bits -> row indices ----
    int f0 = fA ? fstart - (__ffs(fA) - 1) : -1;
    int f1 = fB ? fstart - (__ffs(fB) - 1) : -1;
    int n0i = nA ? bstart + (__ffs(nA) - 1) : -1;
    int n1i = nB ? bstart + (__ffs(nB) - 1) : -1;

    {   // forward fallback: P ~ 2^-12 per lane
        int ti = fstart - PD;
        while ((f0 < 0 || f1 < 0) && ti >= 0) {
            unsigned int a, bb;
            if (isb) {
                unsigned short w = *(const unsigned short*)(m8 + rb + ti * ND);
                a = w & 0xffu; bb = w >> 8;
            } else {
                int2 w = m32[rb2 + ti * (ND / 2)];
                a = w.x; bb = w.y;
            }
            if (f0 < 0 && a)  f0 = ti;
            if (f1 < 0 && bb) f1 = ti;
            --ti;
        }
    }
    {   // backward fallback
        int ti = bstart + PD;
        while ((n0i < 0 || n1i < 0) && ti < NT) {
            unsigned int a, bb;
            if (isb) {
                unsigned short w = *(const unsigned short*)(m8 + rb + ti * ND);
                a = w & 0xffu; bb = w >> 8;
            } else {
                int2 w = m32[rb2 + ti * (ND / 2)];
                a = w.x; bb = w.y;
            }
            if (n0i < 0 && a)  n0i = ti;
            if (n1i < 0 && bb) n1i = ti;
            ++ti;
        }
    }

    // ---- seed gathers (both directions issued together) ----
    float lx0 = 0.f, lx1 = 0.f, lt0, lt1;
    if (f0 >= 0) { lx0 = v[rb + f0 * ND];     lt0 = t[rb + f0 * ND];     } else lt0 = t[rb];
    if (f1 >= 0) { lx1 = v[rb + 1 + f1 * ND]; lt1 = t[rb + 1 + f1 * ND]; } else lt1 = t[rb + 1];
    float nx0 = 0.f, nx1 = 0.f, nt0, nt1;
    if (n0i >= 0) { nx0 = v[rb + n0i * ND];     nt0 = t[rb + n0i * ND];     } else nt0 = t[rb + (NT - 1) * ND];
    if (n1i >= 0) { nx1 = v[rb + 1 + n1i * ND]; nt1 = t[rb + 1 + n1i * ND]; } else nt1 = t[rb + 1 + (NT - 1) * ND];

    // ---- forward sweep: inclusive forward fill into registers ----
    float2 LX[CH], LT[CH];
#pragma unroll
    for (int tt = 0; tt < CH; ++tt) {
        float2 vv = v2[base2 + tt * (ND / 2)];
        float2 tv = t2[base2 + tt * (ND / 2)];
        if ((bA >> tt) & 1u) { lx0 = vv.x; lt0 = tv.x; }
        if ((bB >> tt) & 1u) { lx1 = vv.y; lt1 = tv.y; }
        LX[tt] = make_float2(lx0, lx1);
        LT[tt] = make_float2(lt0, lt1);
    }

    // ---- backward sweep: re-load t (L1 hits), backward fill + interpolate ----
#pragma unroll
    for (int tt = CH - 1; tt >= 0; --tt) {
        float2 tv2 = t2[base2 + tt * (ND / 2)];   // L1 hit: touched in fwd sweep
        float2 o;
        // lane 0
        {
            float xl = LX[tt].x, tl = LT[tt].x, tv = tv2.x;
            float den = nt0 - tl;
            float r = xl + (nx0 - xl) * __fdividef(tv - tl, den);
            bool ok = (den != 0.f) && isfinite(r);
            if ((bA >> tt) & 1u) {
                o.x = xl;                        // observed: forward fill == v
                nx0 = xl; nt0 = tv;
            } else {
                o.x = ok ? r : 0.f;
            }
        }
        // lane 1
        {
            float xl = LX[tt].y, tl = LT[tt].y, tv = tv2.y;
            float den = nt1 - tl;
            float r = xl + (nx1 - xl) * __fdividef(tv - tl, den);
            bool ok = (den != 0.f) && isfinite(r);
            if ((bB >> tt) & 1u) {
                o.y = xl;
                nx1 = xl; nt1 = tv;
            } else {
                o.y = ok ? r : 0.f;
            }
        }
        o2[base2 + tt * (ND / 2)] = o;
    }
}

// ---------------------------------------------------------------------------
extern "C" void kernel_launch(void* const* d_in, const int* in_sizes, int n_in,
                              void* d_out, int out_size) {
    const float* values = (const float*)d_in[0];
    const float* times  = (const float*)d_in[1];
    const void*  mask   = d_in[2];

    (void)n_in; (void)in_sizes; (void)out_size;

    // Single fused launch: streams mask (+probe overage), v, t once;
    // writes out once.
    k_all<<<(NB * NC * (ND / 2)) / 128, 128>>>(values, times, mask, (float*)d_out);
}